// round 10
// baseline (speedup 1.0000x reference)
#include <cuda_runtime.h>
#include <cuda_bf16.h>
#include <cstdint>

// FrameAlignedGNNLayer3D via mma.sync (sm_100-safe HMMA path).
// R10: weight-fragment reuse. Each warp owns M=32 rows (two 16-row chunks);
// every weight ldmatrix serves both chunks -> ~48% less L1TEX ldmatrix traffic
// (R9 profile: L1 54%, dominated by per-warp re-streaming of W1/W2 tiles).
// CTA = 128 threads / 4 warps, 2 persistent CTAs/SM, doubled per-warp mma ILP.

#define S_SLOTS 4
#define TILE 128
#define NTHREADS 128
#define MAX_NODES (1 << 20)

// ---- smem layout (static, ~37KB) ----
#define XPITCH 48      // 16 bf16 (32B) + 16B pad -> conflict-free ldmatrix
#define WPITCH1 48
#define WPITCH2 144    // 64 bf16 (128B) + 16B pad
#define OFF_XHI  0
#define OFF_XLO  (OFF_XHI + 128 * XPITCH)      // 6144
#define OFF_W1H  (OFF_XLO + 128 * XPITCH)      // 12288
#define OFF_W1L  (OFF_W1H + 64 * WPITCH1)      // 15360
#define OFF_W2H  (OFF_W1L + 64 * WPITCH1)      // 18432
#define OFF_W2L  (OFF_W2H + 64 * WPITCH2)      // 27648
#define OFF_B1   (OFF_W2L + 64 * WPITCH2)      // 36864
#define OFF_B2   (OFF_B1 + 256)
#define OFF_W3   (OFF_B2 + 256)                // 64 float2 pairs
#define OFF_B3   (OFF_W3 + 512)
#define SMEM_BYTES (OFF_B3 + 16)

__device__ int g_edge_is_i64;
__device__ float4 g_node_rec[MAX_NODES];   // {x0, x1, x2, theta}

__global__ void init_kernel(float* __restrict__ out, int n,
                            const int* __restrict__ edge32, int n32,
                            const float* __restrict__ x,
                            const float* __restrict__ theta, int nN) {
    int idx = blockIdx.x * blockDim.x + threadIdx.x;
    if (idx < n) out[idx] = 0.0f;
    if (idx < nN) {
        g_node_rec[idx] = make_float4(x[3 * idx + 0], x[3 * idx + 1],
                                      x[3 * idx + 2], theta[idx]);
    }
    if (idx == 0) {
        int any_nonzero = 0;
        for (int s = 0; s < 16; s++) {
            long long pos = 1 + (long long)s * ((n32 - 2) / 16);
            pos |= 1;
            if (pos < n32) any_nonzero |= (edge32[pos] != 0);
        }
        g_edge_is_i64 = any_nonzero ? 0 : 1;
    }
}

// silu via hardware tanh: silu(v) = 0.5v * (1 + tanh(0.5v)). 1 MUFU + 2 FMA.
__device__ __forceinline__ float silu(float v) {
    float h = 0.5f * v;
    float t;
    asm("tanh.approx.f32 %0, %1;" : "=f"(t) : "f"(h));
    return fmaf(h, t, h);
}

__device__ __forceinline__ uint32_t smem_u32(const void* p) {
    uint32_t a;
    asm("{ .reg .u64 t; cvta.to.shared.u64 t, %1; cvt.u32.u64 %0, t; }" : "=r"(a) : "l"(p));
    return a;
}

__device__ __forceinline__ void ldm4(uint32_t addr, uint32_t& r0, uint32_t& r1,
                                     uint32_t& r2, uint32_t& r3) {
    asm volatile("ldmatrix.sync.aligned.m8n8.x4.shared.b16 {%0,%1,%2,%3}, [%4];"
                 : "=r"(r0), "=r"(r1), "=r"(r2), "=r"(r3) : "r"(addr));
}

__device__ __forceinline__ void mma16816(float* c, const uint32_t* a,
                                         uint32_t b0, uint32_t b1) {
    asm volatile(
        "mma.sync.aligned.m16n8k16.row.col.f32.bf16.bf16.f32 "
        "{%0,%1,%2,%3}, {%4,%5,%6,%7}, {%8,%9}, {%0,%1,%2,%3};"
        : "+f"(c[0]), "+f"(c[1]), "+f"(c[2]), "+f"(c[3])
        : "r"(a[0]), "r"(a[1]), "r"(a[2]), "r"(a[3]), "r"(b0), "r"(b1));
}

__device__ __forceinline__ uint32_t pack_bf2(float v0, float v1) {
    __nv_bfloat162 p = __floats2bfloat162_rn(v0, v1);   // .x = v0 (low half)
    return *reinterpret_cast<uint32_t*>(&p);
}

__global__ __launch_bounds__(NTHREADS, 2)
void gnn_mma_kernel(
    const float* __restrict__ H, const int* __restrict__ edge,
    const float* __restrict__ W1, const float* __restrict__ b1,
    const float* __restrict__ W2, const float* __restrict__ b2,
    const float* __restrict__ W3, const float* __restrict__ b3,
    float* __restrict__ out, int nE, int ntiles)
{
    __shared__ __align__(16) char smem[SMEM_BYTES];
    const uint32_t sb = smem_u32(smem);

    const int t    = threadIdx.x;
    const int lane = t & 31;
    const int w    = t >> 5;           // warp id 0..3, rows [32w, 32w+32)
    const int is64 = g_edge_is_i64;
    const long long items = (long long)nE * S_SLOTS;

    // ================= stage weights ONCE per block =================
    for (int idx = t; idx < 64 * 10; idx += NTHREADS) {
        int kk = idx / 64, n = idx % 64;
        float v = W1[kk * 64 + n];
        __nv_bfloat16 hi = __float2bfloat16_rn(v);
        __nv_bfloat16 lo = __float2bfloat16_rn(v - __bfloat162float(hi));
        *(__nv_bfloat16*)(smem + OFF_W1H + n * WPITCH1 + kk * 2) = hi;
        *(__nv_bfloat16*)(smem + OFF_W1L + n * WPITCH1 + kk * 2) = lo;
    }
    if (t < 64) {  // zero pad kk 10..15 of W1
        for (int kk = 10; kk < 16; kk++) {
            *(__nv_bfloat16*)(smem + OFF_W1H + t * WPITCH1 + kk * 2) = __float2bfloat16_rn(0.f);
            *(__nv_bfloat16*)(smem + OFF_W1L + t * WPITCH1 + kk * 2) = __float2bfloat16_rn(0.f);
        }
    }
    for (int idx = t; idx < 64 * 64; idx += NTHREADS) {
        int k = idx >> 6, n = idx & 63;
        float v = W2[k * 64 + n];
        __nv_bfloat16 hi = __float2bfloat16_rn(v);
        __nv_bfloat16 lo = __float2bfloat16_rn(v - __bfloat162float(hi));
        *(__nv_bfloat16*)(smem + OFF_W2H + n * WPITCH2 + k * 2) = hi;
        *(__nv_bfloat16*)(smem + OFF_W2L + n * WPITCH2 + k * 2) = lo;
    }
    if (t < 64) {
        ((float*)(smem + OFF_B1))[t] = b1[t];
        ((float*)(smem + OFF_B2))[t] = b2[t];
        ((float2*)(smem + OFF_W3))[t] = make_float2(W3[2 * t], W3[2 * t + 1]);
    }
    if (t < 2) ((float*)(smem + OFF_B3))[t] = b3[t];

    // ================= ldmatrix address precompute =================
    const int sel = lane >> 3;
    const int r8  = lane & 7;
    const uint32_t a_offA = (uint32_t)((w * 32 + r8 + (sel & 1) * 8) * XPITCH + (sel >> 1) * 16);
    const uint32_t a_offB = a_offA + 16 * XPITCH;
    const uint32_t w1_off = (uint32_t)(((sel >> 1) * 8 + r8) * WPITCH1 + (sel & 1) * 16);
    const uint32_t w2_off = (uint32_t)(((sel >> 1) * 8 + r8) * WPITCH2 + (sel & 1) * 16);
    const int cb = 2 * (lane & 3);

    __syncthreads();

    // ================= persistent tile loop =================
    for (int tile = blockIdx.x; tile < ntiles; tile += gridDim.x) {

        // ---- features (all 128 threads, one row each) ----
        {
            const long long item = (long long)tile * TILE + t;
            float f[10] = {0, 0, 0, 0, 0, 0, 0, 0, 0, 0};
            if (item < items) {
                const int e = (int)(item >> 2);
                const int s = (int)(item & 3);
                int i_node, j_node;
                if (is64) {
                    const long long* e64 = (const long long*)edge;
                    i_node = (int)e64[e]; j_node = (int)e64[(long long)nE + e];
                } else {
                    i_node = edge[e]; j_node = edge[nE + e];
                }
                const float4 ri = g_node_rec[i_node];
                const float4 rj = g_node_rec[j_node];
                const float dx0 = rj.x - ri.x;
                const float dx1 = rj.y - ri.y;
                const float dx2 = rj.z - ri.z;
                const float rxy2 = dx0 * dx0 + dx1 * dx1;
                float s2, c2; sincosf(2.0f * (rj.w - ri.w), &s2, &c2);
                float sp, cp; sincosf(atan2f(dx1, dx0) - ri.w, &sp, &cp);
                const float sgn = (dx2 > 0.0f) ? 1.0f : ((dx2 < 0.0f) ? -1.0f : 0.0f);
                const float2 hv = *(const float2*)(H + ((long long)j_node * S_SLOTS + s) * 2);
                f[0] = c2 * hv.x - s2 * hv.y;
                f[1] = s2 * hv.x + c2 * hv.y;
                f[2] = sqrtf(rxy2 + dx2 * dx2);
                f[3] = sqrtf(rxy2);
                f[4] = dx2;
                f[5] = sp;  f[6] = cp;  f[7] = s2;  f[8] = c2;  f[9] = sgn * s2;
            }
            uint32_t ph[8], pl[8];
            #pragma unroll
            for (int c = 0; c < 10; c += 2) {
                __nv_bfloat16 h0 = __float2bfloat16_rn(f[c]);
                __nv_bfloat16 h1 = __float2bfloat16_rn(f[c + 1]);
                ph[c >> 1] = pack_bf2(__bfloat162float(h0), __bfloat162float(h1));
                pl[c >> 1] = pack_bf2(f[c]     - __bfloat162float(h0),
                                      f[c + 1] - __bfloat162float(h1));
            }
            ph[5] = 0u; ph[6] = 0u; ph[7] = 0u;
            pl[5] = 0u; pl[6] = 0u; pl[7] = 0u;
            uint4* xh = (uint4*)(smem + OFF_XHI + t * XPITCH);
            uint4* xl = (uint4*)(smem + OFF_XLO + t * XPITCH);
            xh[0] = make_uint4(ph[0], ph[1], ph[2], ph[3]);
            xh[1] = make_uint4(ph[4], ph[5], ph[6], ph[7]);
            xl[0] = make_uint4(pl[0], pl[1], pl[2], pl[3]);
            xl[1] = make_uint4(pl[4], pl[5], pl[6], pl[7]);
        }
        __syncthreads();

        // ---- layer 1: X(32 rows x16) @ W1(16x64), both chunks per W-load ----
        float c1A[32], c1B[32];
        #pragma unroll
        for (int i = 0; i < 32; i++) { c1A[i] = 0.0f; c1B[i] = 0.0f; }
        {
            uint32_t aAh[4], aAl[4], aBh[4], aBl[4];
            ldm4(sb + OFF_XHI + a_offA, aAh[0], aAh[1], aAh[2], aAh[3]);
            ldm4(sb + OFF_XLO + a_offA, aAl[0], aAl[1], aAl[2], aAl[3]);
            ldm4(sb + OFF_XHI + a_offB, aBh[0], aBh[1], aBh[2], aBh[3]);
            ldm4(sb + OFF_XLO + a_offB, aBl[0], aBl[1], aBl[2], aBl[3]);
            #pragma unroll
            for (int jp = 0; jp < 8; jp += 2) {
                uint32_t wh0, wh1, wh2, wh3, wl0, wl1, wl2, wl3;
                ldm4(sb + OFF_W1H + jp * 8 * WPITCH1 + w1_off, wh0, wh1, wh2, wh3);
                ldm4(sb + OFF_W1L + jp * 8 * WPITCH1 + w1_off, wl0, wl1, wl2, wl3);
                mma16816(c1A + 4 * jp,     aAh, wh0, wh1);
                mma16816(c1A + 4 * jp,     aAl, wh0, wh1);
                mma16816(c1A + 4 * jp,     aAh, wl0, wl1);
                mma16816(c1A + 4 * jp + 4, aAh, wh2, wh3);
                mma16816(c1A + 4 * jp + 4, aAl, wh2, wh3);
                mma16816(c1A + 4 * jp + 4, aAh, wl2, wl3);
                mma16816(c1B + 4 * jp,     aBh, wh0, wh1);
                mma16816(c1B + 4 * jp,     aBl, wh0, wh1);
                mma16816(c1B + 4 * jp,     aBh, wl0, wl1);
                mma16816(c1B + 4 * jp + 4, aBh, wh2, wh3);
                mma16816(c1B + 4 * jp + 4, aBl, wh2, wh3);
                mma16816(c1B + 4 * jp + 4, aBh, wl2, wl3);
            }
        }

        // ---- layer 2, fused epilogue-1, both chunks share W2 fragments ----
        float c2A[32], c2B[32];
        #pragma unroll
        for (int i = 0; i < 32; i++) { c2A[i] = 0.0f; c2B[i] = 0.0f; }

        #pragma unroll
        for (int q = 0; q < 4; q++) {
            uint32_t a2hA[4], a2lA[4], a2hB[4], a2lB[4];
            #pragma unroll
            for (int jj = 0; jj < 2; jj++) {            // n-tiles j = 2q+jj
                const int cjj = 8 * q + 4 * jj;
                const float2 bia = *(const float2*)(smem + OFF_B1 + (8 * (2 * q + jj) + cb) * 4);
                // chunk A
                {
                    float v0 = silu(c1A[cjj + 0] + bia.x);
                    float v1 = silu(c1A[cjj + 1] + bia.y);
                    float v2 = silu(c1A[cjj + 2] + bia.x);
                    float v3 = silu(c1A[cjj + 3] + bia.y);
                    __nv_bfloat16 h0 = __float2bfloat16_rn(v0), h1 = __float2bfloat16_rn(v1);
                    __nv_bfloat16 h2 = __float2bfloat16_rn(v2), h3 = __float2bfloat16_rn(v3);
                    a2hA[2 * jj + 0] = pack_bf2(__bfloat162float(h0), __bfloat162float(h1));
                    a2hA[2 * jj + 1] = pack_bf2(__bfloat162float(h2), __bfloat162float(h3));
                    a2lA[2 * jj + 0] = pack_bf2(v0 - __bfloat162float(h0), v1 - __bfloat162float(h1));
                    a2lA[2 * jj + 1] = pack_bf2(v2 - __bfloat162float(h2), v3 - __bfloat162float(h3));
                }
                // chunk B
                {
                    float v0 = silu(c1B[cjj + 0] + bia.x);
                    float v1 = silu(c1B[cjj + 1] + bia.y);
                    float v2 = silu(c1B[cjj + 2] + bia.x);
                    float v3 = silu(c1B[cjj + 3] + bia.y);
                    __nv_bfloat16 h0 = __float2bfloat16_rn(v0), h1 = __float2bfloat16_rn(v1);
                    __nv_bfloat16 h2 = __float2bfloat16_rn(v2), h3 = __float2bfloat16_rn(v3);
                    a2hB[2 * jj + 0] = pack_bf2(__bfloat162float(h0), __bfloat162float(h1));
                    a2hB[2 * jj + 1] = pack_bf2(__bfloat162float(h2), __bfloat162float(h3));
                    a2lB[2 * jj + 0] = pack_bf2(v0 - __bfloat162float(h0), v1 - __bfloat162float(h1));
                    a2lB[2 * jj + 1] = pack_bf2(v2 - __bfloat162float(h2), v3 - __bfloat162float(h3));
                }
            }
            #pragma unroll
            for (int jp = 0; jp < 8; jp += 2) {
                uint32_t wh0, wh1, wh2, wh3, wl0, wl1, wl2, wl3;
                ldm4(sb + OFF_W2H + jp * 8 * WPITCH2 + q * 32 + w2_off, wh0, wh1, wh2, wh3);
                ldm4(sb + OFF_W2L + jp * 8 * WPITCH2 + q * 32 + w2_off, wl0, wl1, wl2, wl3);
                mma16816(c2A + 4 * jp,     a2hA, wh0, wh1);
                mma16816(c2A + 4 * jp,     a2lA, wh0, wh1);
                mma16816(c2A + 4 * jp,     a2hA, wl0, wl1);
                mma16816(c2A + 4 * jp + 4, a2hA, wh2, wh3);
                mma16816(c2A + 4 * jp + 4, a2lA, wh2, wh3);
                mma16816(c2A + 4 * jp + 4, a2hA, wl2, wl3);
                mma16816(c2B + 4 * jp,     a2hB, wh0, wh1);
                mma16816(c2B + 4 * jp,     a2lB, wh0, wh1);
                mma16816(c2B + 4 * jp,     a2hB, wl0, wl1);
                mma16816(c2B + 4 * jp + 4, a2hB, wh2, wh3);
                mma16816(c2B + 4 * jp + 4, a2lB, wh2, wh3);
                mma16816(c2B + 4 * jp + 4, a2hB, wl2, wl3);
            }
        }

        // ---- epilogue 2 for both chunks: silu + layer3 + reduce + scatter ----
        #pragma unroll
        for (int chunk = 0; chunk < 2; chunk++) {
            const float* c2 = chunk ? c2B : c2A;
            float o0a = 0.f, o1a = 0.f, o0b = 0.f, o1b = 0.f;
            #pragma unroll
            for (int j = 0; j < 8; j++) {
                const int c0 = 8 * j + cb;
                const float2 bia = *(const float2*)(smem + OFF_B2 + c0 * 4);
                const float2 w3a = *(const float2*)(smem + OFF_W3 + c0 * 8);
                const float2 w3b = *(const float2*)(smem + OFF_W3 + (c0 + 1) * 8);
                float v0 = silu(c2[4 * j + 0] + bia.x);
                float v1 = silu(c2[4 * j + 1] + bia.y);
                float v2 = silu(c2[4 * j + 2] + bia.x);
                float v3 = silu(c2[4 * j + 3] + bia.y);
                o0a = fmaf(v0, w3a.x, fmaf(v1, w3b.x, o0a));
                o1a = fmaf(v0, w3a.y, fmaf(v1, w3b.y, o1a));
                o0b = fmaf(v2, w3a.x, fmaf(v3, w3b.x, o0b));
                o1b = fmaf(v2, w3a.y, fmaf(v3, w3b.y, o1b));
            }
            #pragma unroll
            for (int m = 1; m <= 2; m <<= 1) {
                o0a += __shfl_xor_sync(0xffffffffu, o0a, m);
                o1a += __shfl_xor_sync(0xffffffffu, o1a, m);
                o0b += __shfl_xor_sync(0xffffffffu, o0b, m);
                o1b += __shfl_xor_sync(0xffffffffu, o1b, m);
            }
            if ((lane & 3) == 0) {
                const float bb0 = ((float*)(smem + OFF_B3))[0];
                const float bb1 = ((float*)(smem + OFF_B3))[1];
                const int g = lane >> 2;
                #pragma unroll
                for (int half = 0; half < 2; half++) {
                    const long long item = (long long)tile * TILE + w * 32 + chunk * 16
                                         + g + 8 * half;
                    if (item < items) {
                        const int e = (int)(item >> 2);
                        const int s = (int)(item & 3);
                        int i_node;
                        if (is64) i_node = (int)((const long long*)edge)[e];
                        else      i_node = edge[e];
                        float* o = out + ((long long)i_node * S_SLOTS + s) * 2;
                        atomicAdd(o + 0, (half ? o0b : o0a) + bb0);
                        atomicAdd(o + 1, (half ? o1b : o1a) + bb1);
                    }
                }
            }
        }
        __syncthreads();   // protect X tiles before next iteration's writes
    }
}

extern "C" void kernel_launch(void* const* d_in, const int* in_sizes, int n_in,
                              void* d_out, int out_size) {
    const float* x     = (const float*)d_in[0];
    const float* theta = (const float*)d_in[1];
    const float* H     = (const float*)d_in[2];
    const int*   edge  = (const int*)d_in[3];
    const float* W1    = (const float*)d_in[4];
    const float* b1    = (const float*)d_in[5];
    const float* W2    = (const float*)d_in[6];
    const float* b2    = (const float*)d_in[7];
    const float* W3    = (const float*)d_in[8];
    const float* b3    = (const float*)d_in[9];

    const int nE = in_sizes[3] / 2;
    int nN = in_sizes[1];                  // theta has N elements
    if (nN > MAX_NODES) nN = MAX_NODES;

    const int init_n = (out_size > nN) ? out_size : nN;
    init_kernel<<<(init_n + 255) / 256, 256>>>((float*)d_out, out_size,
                                               edge, in_sizes[3], x, theta, nN);

    const long long items = (long long)nE * S_SLOTS;
    const int ntiles = (int)((items + TILE - 1) / TILE);
    int grid = 2 * 148;                    // 2 persistent CTAs per SM
    if (grid > ntiles) grid = ntiles;
    gnn_mma_kernel<<<grid, NTHREADS>>>(H, edge,
                                       W1, b1, W2, b2, W3, b3,
                                       (float*)d_out, nE, ntiles);
}

// round 11
// speedup vs baseline: 1.1403x; 1.1403x over previous
#include <cuda_runtime.h>
#include <cuda_fp16.h>
#include <cstdint>

// FrameAlignedGNNLayer3D via mma.sync (sm_100-safe HMMA path).
// R11: fp16 2-term split replaces bf16 3-term. mma count -33% (the invariant
// binding resource per R8-R10 profiles: tensor pinned at 47% while L1 and
// occupancy changes did nothing). Weights single-fp16 (error ~2^-12 RMS ->
// predicted rel_err 2-4e-4, gate 1e-3); activations fp16 hi+lo (22 bits).
// Weight smem + weight ldmatrix halve as a side effect.

#define S_SLOTS 4
#define TILE 128
#define NTHREADS 128
#define MAX_NODES (1 << 20)

// ---- smem layout (static, ~25KB) ----
#define XPITCH 48      // 16 fp16 (32B) + 16B pad -> conflict-free ldmatrix
#define WPITCH1 48
#define WPITCH2 144    // 64 fp16 (128B) + 16B pad
#define OFF_XHI  0
#define OFF_XLO  (OFF_XHI + 128 * XPITCH)      // 6144
#define OFF_W1H  (OFF_XLO + 128 * XPITCH)      // 12288
#define OFF_W2H  (OFF_W1H + 64 * WPITCH1)      // 15360
#define OFF_B1   (OFF_W2H + 64 * WPITCH2)      // 24576
#define OFF_B2   (OFF_B1 + 256)
#define OFF_W3   (OFF_B2 + 256)                // 64 float2 pairs
#define OFF_B3   (OFF_W3 + 512)
#define SMEM_BYTES (OFF_B3 + 16)

__device__ int g_edge_is_i64;
__device__ float4 g_node_rec[MAX_NODES];   // {x0, x1, x2, theta}

__global__ void init_kernel(float* __restrict__ out, int n,
                            const int* __restrict__ edge32, int n32,
                            const float* __restrict__ x,
                            const float* __restrict__ theta, int nN) {
    int idx = blockIdx.x * blockDim.x + threadIdx.x;
    if (idx < n) out[idx] = 0.0f;
    if (idx < nN) {
        g_node_rec[idx] = make_float4(x[3 * idx + 0], x[3 * idx + 1],
                                      x[3 * idx + 2], theta[idx]);
    }
    if (idx == 0) {
        int any_nonzero = 0;
        for (int s = 0; s < 16; s++) {
            long long pos = 1 + (long long)s * ((n32 - 2) / 16);
            pos |= 1;
            if (pos < n32) any_nonzero |= (edge32[pos] != 0);
        }
        g_edge_is_i64 = any_nonzero ? 0 : 1;
    }
}

// silu via hardware tanh: silu(v) = 0.5v * (1 + tanh(0.5v)). 1 MUFU + 2 FMA.
__device__ __forceinline__ float silu(float v) {
    float h = 0.5f * v;
    float t;
    asm("tanh.approx.f32 %0, %1;" : "=f"(t) : "f"(h));
    return fmaf(h, t, h);
}

__device__ __forceinline__ uint32_t smem_u32(const void* p) {
    uint32_t a;
    asm("{ .reg .u64 t; cvta.to.shared.u64 t, %1; cvt.u32.u64 %0, t; }" : "=r"(a) : "l"(p));
    return a;
}

__device__ __forceinline__ void ldm4(uint32_t addr, uint32_t& r0, uint32_t& r1,
                                     uint32_t& r2, uint32_t& r3) {
    asm volatile("ldmatrix.sync.aligned.m8n8.x4.shared.b16 {%0,%1,%2,%3}, [%4];"
                 : "=r"(r0), "=r"(r1), "=r"(r2), "=r"(r3) : "r"(addr));
}

__device__ __forceinline__ void mma16816(float* c, const uint32_t* a,
                                         uint32_t b0, uint32_t b1) {
    asm volatile(
        "mma.sync.aligned.m16n8k16.row.col.f32.f16.f16.f32 "
        "{%0,%1,%2,%3}, {%4,%5,%6,%7}, {%8,%9}, {%0,%1,%2,%3};"
        : "+f"(c[0]), "+f"(c[1]), "+f"(c[2]), "+f"(c[3])
        : "r"(a[0]), "r"(a[1]), "r"(a[2]), "r"(a[3]), "r"(b0), "r"(b1));
}

__device__ __forceinline__ uint32_t pack_hf2(float v0, float v1) {
    __half2 p = __floats2half2_rn(v0, v1);   // .x = v0 (low half)
    return *reinterpret_cast<uint32_t*>(&p);
}

__global__ __launch_bounds__(NTHREADS, 2)
void gnn_mma_kernel(
    const float* __restrict__ H, const int* __restrict__ edge,
    const float* __restrict__ W1, const float* __restrict__ b1,
    const float* __restrict__ W2, const float* __restrict__ b2,
    const float* __restrict__ W3, const float* __restrict__ b3,
    float* __restrict__ out, int nE, int ntiles)
{
    __shared__ __align__(16) char smem[SMEM_BYTES];
    const uint32_t sb = smem_u32(smem);

    const int t    = threadIdx.x;
    const int lane = t & 31;
    const int w    = t >> 5;           // warp id 0..3, rows [32w, 32w+32)
    const int is64 = g_edge_is_i64;
    const long long items = (long long)nE * S_SLOTS;

    // ================= stage weights ONCE per block (single fp16) ============
    for (int idx = t; idx < 64 * 10; idx += NTHREADS) {
        int kk = idx / 64, n = idx % 64;
        *(__half*)(smem + OFF_W1H + n * WPITCH1 + kk * 2) = __float2half_rn(W1[kk * 64 + n]);
    }
    if (t < 64) {  // zero pad kk 10..15 of W1
        for (int kk = 10; kk < 16; kk++)
            *(__half*)(smem + OFF_W1H + t * WPITCH1 + kk * 2) = __float2half_rn(0.f);
    }
    for (int idx = t; idx < 64 * 64; idx += NTHREADS) {
        int k = idx >> 6, n = idx & 63;
        *(__half*)(smem + OFF_W2H + n * WPITCH2 + k * 2) = __float2half_rn(W2[k * 64 + n]);
    }
    if (t < 64) {
        ((float*)(smem + OFF_B1))[t] = b1[t];
        ((float*)(smem + OFF_B2))[t] = b2[t];
        ((float2*)(smem + OFF_W3))[t] = make_float2(W3[2 * t], W3[2 * t + 1]);
    }
    if (t < 2) ((float*)(smem + OFF_B3))[t] = b3[t];

    // ================= ldmatrix address precompute =================
    const int sel = lane >> 3;
    const int r8  = lane & 7;
    const uint32_t a_offA = (uint32_t)((w * 32 + r8 + (sel & 1) * 8) * XPITCH + (sel >> 1) * 16);
    const uint32_t a_offB = a_offA + 16 * XPITCH;
    const uint32_t w1_off = (uint32_t)(((sel >> 1) * 8 + r8) * WPITCH1 + (sel & 1) * 16);
    const uint32_t w2_off = (uint32_t)(((sel >> 1) * 8 + r8) * WPITCH2 + (sel & 1) * 16);
    const int cb = 2 * (lane & 3);

    __syncthreads();

    // ================= persistent tile loop =================
    for (int tile = blockIdx.x; tile < ntiles; tile += gridDim.x) {

        // ---- features (all 128 threads, one row each) ----
        {
            const long long item = (long long)tile * TILE + t;
            float f[10] = {0, 0, 0, 0, 0, 0, 0, 0, 0, 0};
            if (item < items) {
                const int e = (int)(item >> 2);
                const int s = (int)(item & 3);
                int i_node, j_node;
                if (is64) {
                    const long long* e64 = (const long long*)edge;
                    i_node = (int)e64[e]; j_node = (int)e64[(long long)nE + e];
                } else {
                    i_node = edge[e]; j_node = edge[nE + e];
                }
                const float4 ri = g_node_rec[i_node];
                const float4 rj = g_node_rec[j_node];
                const float dx0 = rj.x - ri.x;
                const float dx1 = rj.y - ri.y;
                const float dx2 = rj.z - ri.z;
                const float rxy2 = dx0 * dx0 + dx1 * dx1;
                float s2, c2; sincosf(2.0f * (rj.w - ri.w), &s2, &c2);
                float sp, cp; sincosf(atan2f(dx1, dx0) - ri.w, &sp, &cp);
                const float sgn = (dx2 > 0.0f) ? 1.0f : ((dx2 < 0.0f) ? -1.0f : 0.0f);
                const float2 hv = *(const float2*)(H + ((long long)j_node * S_SLOTS + s) * 2);
                f[0] = c2 * hv.x - s2 * hv.y;
                f[1] = s2 * hv.x + c2 * hv.y;
                f[2] = sqrtf(rxy2 + dx2 * dx2);
                f[3] = sqrtf(rxy2);
                f[4] = dx2;
                f[5] = sp;  f[6] = cp;  f[7] = s2;  f[8] = c2;  f[9] = sgn * s2;
            }
            uint32_t ph[8], pl[8];
            #pragma unroll
            for (int c = 0; c < 10; c += 2) {
                float h0 = __half2float(__float2half_rn(f[c]));
                float h1 = __half2float(__float2half_rn(f[c + 1]));
                ph[c >> 1] = pack_hf2(h0, h1);
                pl[c >> 1] = pack_hf2(f[c] - h0, f[c + 1] - h1);
            }
            ph[5] = 0u; ph[6] = 0u; ph[7] = 0u;
            pl[5] = 0u; pl[6] = 0u; pl[7] = 0u;
            uint4* xh = (uint4*)(smem + OFF_XHI + t * XPITCH);
            uint4* xl = (uint4*)(smem + OFF_XLO + t * XPITCH);
            xh[0] = make_uint4(ph[0], ph[1], ph[2], ph[3]);
            xh[1] = make_uint4(ph[4], ph[5], ph[6], ph[7]);
            xl[0] = make_uint4(pl[0], pl[1], pl[2], pl[3]);
            xl[1] = make_uint4(pl[4], pl[5], pl[6], pl[7]);
        }
        __syncthreads();

        // ---- layer 1: X(32 rows x16) @ W1(16x64), 2-term fp16 ----
        float c1A[32], c1B[32];
        #pragma unroll
        for (int i = 0; i < 32; i++) { c1A[i] = 0.0f; c1B[i] = 0.0f; }
        {
            uint32_t aAh[4], aAl[4], aBh[4], aBl[4];
            ldm4(sb + OFF_XHI + a_offA, aAh[0], aAh[1], aAh[2], aAh[3]);
            ldm4(sb + OFF_XLO + a_offA, aAl[0], aAl[1], aAl[2], aAl[3]);
            ldm4(sb + OFF_XHI + a_offB, aBh[0], aBh[1], aBh[2], aBh[3]);
            ldm4(sb + OFF_XLO + a_offB, aBl[0], aBl[1], aBl[2], aBl[3]);
            #pragma unroll
            for (int jp = 0; jp < 8; jp += 2) {
                uint32_t wh0, wh1, wh2, wh3;
                ldm4(sb + OFF_W1H + jp * 8 * WPITCH1 + w1_off, wh0, wh1, wh2, wh3);
                mma16816(c1A + 4 * jp,     aAh, wh0, wh1);
                mma16816(c1A + 4 * jp,     aAl, wh0, wh1);
                mma16816(c1A + 4 * jp + 4, aAh, wh2, wh3);
                mma16816(c1A + 4 * jp + 4, aAl, wh2, wh3);
                mma16816(c1B + 4 * jp,     aBh, wh0, wh1);
                mma16816(c1B + 4 * jp,     aBl, wh0, wh1);
                mma16816(c1B + 4 * jp + 4, aBh, wh2, wh3);
                mma16816(c1B + 4 * jp + 4, aBl, wh2, wh3);
            }
        }

        // ---- layer 2, fused epilogue-1, 2-term fp16, shared W2 frags ----
        float c2A[32], c2B[32];
        #pragma unroll
        for (int i = 0; i < 32; i++) { c2A[i] = 0.0f; c2B[i] = 0.0f; }

        #pragma unroll
        for (int q = 0; q < 4; q++) {
            uint32_t a2hA[4], a2lA[4], a2hB[4], a2lB[4];
            #pragma unroll
            for (int jj = 0; jj < 2; jj++) {            // n-tiles j = 2q+jj
                const int cjj = 8 * q + 4 * jj;
                const float2 bia = *(const float2*)(smem + OFF_B1 + (8 * (2 * q + jj) + cb) * 4);
                // chunk A
                {
                    float v0 = silu(c1A[cjj + 0] + bia.x);
                    float v1 = silu(c1A[cjj + 1] + bia.y);
                    float v2 = silu(c1A[cjj + 2] + bia.x);
                    float v3 = silu(c1A[cjj + 3] + bia.y);
                    float h0 = __half2float(__float2half_rn(v0));
                    float h1 = __half2float(__float2half_rn(v1));
                    float h2 = __half2float(__float2half_rn(v2));
                    float h3 = __half2float(__float2half_rn(v3));
                    a2hA[2 * jj + 0] = pack_hf2(h0, h1);
                    a2hA[2 * jj + 1] = pack_hf2(h2, h3);
                    a2lA[2 * jj + 0] = pack_hf2(v0 - h0, v1 - h1);
                    a2lA[2 * jj + 1] = pack_hf2(v2 - h2, v3 - h3);
                }
                // chunk B
                {
                    float v0 = silu(c1B[cjj + 0] + bia.x);
                    float v1 = silu(c1B[cjj + 1] + bia.y);
                    float v2 = silu(c1B[cjj + 2] + bia.x);
                    float v3 = silu(c1B[cjj + 3] + bia.y);
                    float h0 = __half2float(__float2half_rn(v0));
                    float h1 = __half2float(__float2half_rn(v1));
                    float h2 = __half2float(__float2half_rn(v2));
                    float h3 = __half2float(__float2half_rn(v3));
                    a2hB[2 * jj + 0] = pack_hf2(h0, h1);
                    a2hB[2 * jj + 1] = pack_hf2(h2, h3);
                    a2lB[2 * jj + 0] = pack_hf2(v0 - h0, v1 - h1);
                    a2lB[2 * jj + 1] = pack_hf2(v2 - h2, v3 - h3);
                }
            }
            #pragma unroll
            for (int jp = 0; jp < 8; jp += 2) {
                uint32_t wh0, wh1, wh2, wh3;
                ldm4(sb + OFF_W2H + jp * 8 * WPITCH2 + q * 32 + w2_off, wh0, wh1, wh2, wh3);
                mma16816(c2A + 4 * jp,     a2hA, wh0, wh1);
                mma16816(c2A + 4 * jp,     a2lA, wh0, wh1);
                mma16816(c2A + 4 * jp + 4, a2hA, wh2, wh3);
                mma16816(c2A + 4 * jp + 4, a2lA, wh2, wh3);
                mma16816(c2B + 4 * jp,     a2hB, wh0, wh1);
                mma16816(c2B + 4 * jp,     a2lB, wh0, wh1);
                mma16816(c2B + 4 * jp + 4, a2hB, wh2, wh3);
                mma16816(c2B + 4 * jp + 4, a2lB, wh2, wh3);
            }
        }

        // ---- epilogue 2 for both chunks: silu + layer3 + reduce + scatter ----
        #pragma unroll
        for (int chunk = 0; chunk < 2; chunk++) {
            const float* c2 = chunk ? c2B : c2A;
            float o0a = 0.f, o1a = 0.f, o0b = 0.f, o1b = 0.f;
            #pragma unroll
            for (int j = 0; j < 8; j++) {
                const int c0 = 8 * j + cb;
                const float2 bia = *(const float2*)(smem + OFF_B2 + c0 * 4);
                const float2 w3a = *(const float2*)(smem + OFF_W3 + c0 * 8);
                const float2 w3b = *(const float2*)(smem + OFF_W3 + (c0 + 1) * 8);
                float v0 = silu(c2[4 * j + 0] + bia.x);
                float v1 = silu(c2[4 * j + 1] + bia.y);
                float v2 = silu(c2[4 * j + 2] + bia.x);
                float v3 = silu(c2[4 * j + 3] + bia.y);
                o0a = fmaf(v0, w3a.x, fmaf(v1, w3b.x, o0a));
                o1a = fmaf(v0, w3a.y, fmaf(v1, w3b.y, o1a));
                o0b = fmaf(v2, w3a.x, fmaf(v3, w3b.x, o0b));
                o1b = fmaf(v2, w3a.y, fmaf(v3, w3b.y, o1b));
            }
            #pragma unroll
            for (int m = 1; m <= 2; m <<= 1) {
                o0a += __shfl_xor_sync(0xffffffffu, o0a, m);
                o1a += __shfl_xor_sync(0xffffffffu, o1a, m);
                o0b += __shfl_xor_sync(0xffffffffu, o0b, m);
                o1b += __shfl_xor_sync(0xffffffffu, o1b, m);
            }
            if ((lane & 3) == 0) {
                const float bb0 = ((float*)(smem + OFF_B3))[0];
                const float bb1 = ((float*)(smem + OFF_B3))[1];
                const int g = lane >> 2;
                #pragma unroll
                for (int half = 0; half < 2; half++) {
                    const long long item = (long long)tile * TILE + w * 32 + chunk * 16
                                         + g + 8 * half;
                    if (item < items) {
                        const int e = (int)(item >> 2);
                        const int s = (int)(item & 3);
                        int i_node;
                        if (is64) i_node = (int)((const long long*)edge)[e];
                        else      i_node = edge[e];
                        float* o = out + ((long long)i_node * S_SLOTS + s) * 2;
                        atomicAdd(o + 0, (half ? o0b : o0a) + bb0);
                        atomicAdd(o + 1, (half ? o1b : o1a) + bb1);
                    }
                }
            }
        }
        __syncthreads();   // protect X tiles before next iteration's writes
    }
}

extern "C" void kernel_launch(void* const* d_in, const int* in_sizes, int n_in,
                              void* d_out, int out_size) {
    const float* x     = (const float*)d_in[0];
    const float* theta = (const float*)d_in[1];
    const float* H     = (const float*)d_in[2];
    const int*   edge  = (const int*)d_in[3];
    const float* W1    = (const float*)d_in[4];
    const float* b1    = (const float*)d_in[5];
    const float* W2    = (const float*)d_in[6];
    const float* b2    = (const float*)d_in[7];
    const float* W3    = (const float*)d_in[8];
    const float* b3    = (const float*)d_in[9];

    const int nE = in_sizes[3] / 2;
    int nN = in_sizes[1];                  // theta has N elements
    if (nN > MAX_NODES) nN = MAX_NODES;

    const int init_n = (out_size > nN) ? out_size : nN;
    init_kernel<<<(init_n + 255) / 256, 256>>>((float*)d_out, out_size,
                                               edge, in_sizes[3], x, theta, nN);

    const long long items = (long long)nE * S_SLOTS;
    const int ntiles = (int)((items + TILE - 1) / TILE);
    int grid = 2 * 148;                    // 2 persistent CTAs per SM
    if (grid > ntiles) grid = ntiles;
    gnn_mma_kernel<<<grid, NTHREADS>>>(H, edge,
                                       W1, b1, W2, b2, W3, b3,
                                       (float*)d_out, nE, ntiles);
}

// round 12
// speedup vs baseline: 1.1687x; 1.0249x over previous
#include <cuda_runtime.h>
#include <cuda_fp16.h>
#include <cstdint>

// FrameAlignedGNNLayer3D via mma.sync (sm_100-safe HMMA path).
// R12: revert R10's M=32/warp shape (which cost 64 accumulator regs and pinned
// occupancy at 12.4% -> latency-bound per R11 profile: no pipe >42% issue).
// Back to 256 thr / 8 warps / M=16 rows per warp; keep R11's fp16 2-term split.
// Regs ~115 -> 2 CTAs/SM = 16 warps = 24% occ, doubling latency hiding.

#define S_SLOTS 4
#define TILE 128
#define NTHREADS 256
#define MAX_NODES (1 << 20)

// ---- smem layout (static, ~25KB) ----
#define XPITCH 48      // 16 fp16 (32B) + 16B pad -> conflict-free ldmatrix
#define WPITCH1 48
#define WPITCH2 144    // 64 fp16 (128B) + 16B pad
#define OFF_XHI  0
#define OFF_XLO  (OFF_XHI + 128 * XPITCH)      // 6144
#define OFF_W1H  (OFF_XLO + 128 * XPITCH)      // 12288
#define OFF_W2H  (OFF_W1H + 64 * WPITCH1)      // 15360
#define OFF_B1   (OFF_W2H + 64 * WPITCH2)      // 24576
#define OFF_B2   (OFF_B1 + 256)
#define OFF_W3   (OFF_B2 + 256)                // 64 float2 pairs
#define OFF_B3   (OFF_W3 + 512)
#define SMEM_BYTES (OFF_B3 + 16)

__device__ int g_edge_is_i64;
__device__ float4 g_node_rec[MAX_NODES];   // {x0, x1, x2, theta}

__global__ void init_kernel(float* __restrict__ out, int n,
                            const int* __restrict__ edge32, int n32,
                            const float* __restrict__ x,
                            const float* __restrict__ theta, int nN) {
    int idx = blockIdx.x * blockDim.x + threadIdx.x;
    if (idx < n) out[idx] = 0.0f;
    if (idx < nN) {
        g_node_rec[idx] = make_float4(x[3 * idx + 0], x[3 * idx + 1],
                                      x[3 * idx + 2], theta[idx]);
    }
    if (idx == 0) {
        int any_nonzero = 0;
        for (int s = 0; s < 16; s++) {
            long long pos = 1 + (long long)s * ((n32 - 2) / 16);
            pos |= 1;
            if (pos < n32) any_nonzero |= (edge32[pos] != 0);
        }
        g_edge_is_i64 = any_nonzero ? 0 : 1;
    }
}

// silu via hardware tanh: silu(v) = 0.5v * (1 + tanh(0.5v)). 1 MUFU + 2 FMA.
__device__ __forceinline__ float silu(float v) {
    float h = 0.5f * v;
    float t;
    asm("tanh.approx.f32 %0, %1;" : "=f"(t) : "f"(h));
    return fmaf(h, t, h);
}

__device__ __forceinline__ uint32_t smem_u32(const void* p) {
    uint32_t a;
    asm("{ .reg .u64 t; cvta.to.shared.u64 t, %1; cvt.u32.u64 %0, t; }" : "=r"(a) : "l"(p));
    return a;
}

__device__ __forceinline__ void ldm4(uint32_t addr, uint32_t& r0, uint32_t& r1,
                                     uint32_t& r2, uint32_t& r3) {
    asm volatile("ldmatrix.sync.aligned.m8n8.x4.shared.b16 {%0,%1,%2,%3}, [%4];"
                 : "=r"(r0), "=r"(r1), "=r"(r2), "=r"(r3) : "r"(addr));
}

__device__ __forceinline__ void mma16816(float* c, const uint32_t* a,
                                         uint32_t b0, uint32_t b1) {
    asm volatile(
        "mma.sync.aligned.m16n8k16.row.col.f32.f16.f16.f32 "
        "{%0,%1,%2,%3}, {%4,%5,%6,%7}, {%8,%9}, {%0,%1,%2,%3};"
        : "+f"(c[0]), "+f"(c[1]), "+f"(c[2]), "+f"(c[3])
        : "r"(a[0]), "r"(a[1]), "r"(a[2]), "r"(a[3]), "r"(b0), "r"(b1));
}

__device__ __forceinline__ uint32_t pack_hf2(float v0, float v1) {
    __half2 p = __floats2half2_rn(v0, v1);   // .x = v0 (low half)
    return *reinterpret_cast<uint32_t*>(&p);
}

__global__ __launch_bounds__(NTHREADS, 2)
void gnn_mma_kernel(
    const float* __restrict__ H, const int* __restrict__ edge,
    const float* __restrict__ W1, const float* __restrict__ b1,
    const float* __restrict__ W2, const float* __restrict__ b2,
    const float* __restrict__ W3, const float* __restrict__ b3,
    float* __restrict__ out, int nE, int ntiles)
{
    __shared__ __align__(16) char smem[SMEM_BYTES];
    const uint32_t sb = smem_u32(smem);

    const int t    = threadIdx.x;
    const int lane = t & 31;
    const int w    = t >> 5;           // warp id 0..7, rows [16w, 16w+16)
    const int is64 = g_edge_is_i64;
    const long long items = (long long)nE * S_SLOTS;

    // ================= stage weights ONCE per block (single fp16) ============
    for (int idx = t; idx < 64 * 10; idx += NTHREADS) {
        int kk = idx / 64, n = idx % 64;
        *(__half*)(smem + OFF_W1H + n * WPITCH1 + kk * 2) = __float2half_rn(W1[kk * 64 + n]);
    }
    if (t < 64) {  // zero pad kk 10..15 of W1
        for (int kk = 10; kk < 16; kk++)
            *(__half*)(smem + OFF_W1H + t * WPITCH1 + kk * 2) = __float2half_rn(0.f);
    }
    for (int idx = t; idx < 64 * 64; idx += NTHREADS) {
        int k = idx >> 6, n = idx & 63;
        *(__half*)(smem + OFF_W2H + n * WPITCH2 + k * 2) = __float2half_rn(W2[k * 64 + n]);
    }
    if (t < 64) {
        ((float*)(smem + OFF_B1))[t] = b1[t];
        ((float*)(smem + OFF_B2))[t] = b2[t];
        ((float2*)(smem + OFF_W3))[t] = make_float2(W3[2 * t], W3[2 * t + 1]);
    }
    if (t < 2) ((float*)(smem + OFF_B3))[t] = b3[t];

    // ================= ldmatrix address precompute =================
    const int sel = lane >> 3;
    const int r8  = lane & 7;
    const uint32_t a_off  = (uint32_t)((w * 16 + r8 + (sel & 1) * 8) * XPITCH + (sel >> 1) * 16);
    const uint32_t w1_off = (uint32_t)(((sel >> 1) * 8 + r8) * WPITCH1 + (sel & 1) * 16);
    const uint32_t w2_off = (uint32_t)(((sel >> 1) * 8 + r8) * WPITCH2 + (sel & 1) * 16);
    const int cb = 2 * (lane & 3);

    __syncthreads();

    // ================= persistent tile loop =================
    for (int tile = blockIdx.x; tile < ntiles; tile += gridDim.x) {

        // ---- features (t < 128, one row each) ----
        if (t < TILE) {
            const long long item = (long long)tile * TILE + t;
            float f[10] = {0, 0, 0, 0, 0, 0, 0, 0, 0, 0};
            if (item < items) {
                const int e = (int)(item >> 2);
                const int s = (int)(item & 3);
                int i_node, j_node;
                if (is64) {
                    const long long* e64 = (const long long*)edge;
                    i_node = (int)e64[e]; j_node = (int)e64[(long long)nE + e];
                } else {
                    i_node = edge[e]; j_node = edge[nE + e];
                }
                const float4 ri = g_node_rec[i_node];
                const float4 rj = g_node_rec[j_node];
                const float dx0 = rj.x - ri.x;
                const float dx1 = rj.y - ri.y;
                const float dx2 = rj.z - ri.z;
                const float rxy2 = dx0 * dx0 + dx1 * dx1;
                float s2, c2; sincosf(2.0f * (rj.w - ri.w), &s2, &c2);
                float sp, cp; sincosf(atan2f(dx1, dx0) - ri.w, &sp, &cp);
                const float sgn = (dx2 > 0.0f) ? 1.0f : ((dx2 < 0.0f) ? -1.0f : 0.0f);
                const float2 hv = *(const float2*)(H + ((long long)j_node * S_SLOTS + s) * 2);
                f[0] = c2 * hv.x - s2 * hv.y;
                f[1] = s2 * hv.x + c2 * hv.y;
                f[2] = sqrtf(rxy2 + dx2 * dx2);
                f[3] = sqrtf(rxy2);
                f[4] = dx2;
                f[5] = sp;  f[6] = cp;  f[7] = s2;  f[8] = c2;  f[9] = sgn * s2;
            }
            uint32_t ph[8], pl[8];
            #pragma unroll
            for (int c = 0; c < 10; c += 2) {
                float h0 = __half2float(__float2half_rn(f[c]));
                float h1 = __half2float(__float2half_rn(f[c + 1]));
                ph[c >> 1] = pack_hf2(h0, h1);
                pl[c >> 1] = pack_hf2(f[c] - h0, f[c + 1] - h1);
            }
            ph[5] = 0u; ph[6] = 0u; ph[7] = 0u;
            pl[5] = 0u; pl[6] = 0u; pl[7] = 0u;
            uint4* xh = (uint4*)(smem + OFF_XHI + t * XPITCH);
            uint4* xl = (uint4*)(smem + OFF_XLO + t * XPITCH);
            xh[0] = make_uint4(ph[0], ph[1], ph[2], ph[3]);
            xh[1] = make_uint4(ph[4], ph[5], ph[6], ph[7]);
            xl[0] = make_uint4(pl[0], pl[1], pl[2], pl[3]);
            xl[1] = make_uint4(pl[4], pl[5], pl[6], pl[7]);
        }
        __syncthreads();

        // ---- layer 1: X(16 rows x16) @ W1(16x64), 2-term fp16 ----
        float c1[32];
        #pragma unroll
        for (int i = 0; i < 32; i++) c1[i] = 0.0f;
        {
            uint32_t a1h[4], a1l[4];
            ldm4(sb + OFF_XHI + a_off, a1h[0], a1h[1], a1h[2], a1h[3]);
            ldm4(sb + OFF_XLO + a_off, a1l[0], a1l[1], a1l[2], a1l[3]);
            #pragma unroll
            for (int jp = 0; jp < 8; jp += 2) {
                uint32_t wh0, wh1, wh2, wh3;
                ldm4(sb + OFF_W1H + jp * 8 * WPITCH1 + w1_off, wh0, wh1, wh2, wh3);
                mma16816(c1 + 4 * jp,     a1h, wh0, wh1);
                mma16816(c1 + 4 * jp,     a1l, wh0, wh1);
                mma16816(c1 + 4 * jp + 4, a1h, wh2, wh3);
                mma16816(c1 + 4 * jp + 4, a1l, wh2, wh3);
            }
        }

        // ---- layer 2, fused epilogue-1, 2-term fp16 ----
        float c2acc[32];
        #pragma unroll
        for (int i = 0; i < 32; i++) c2acc[i] = 0.0f;

        #pragma unroll
        for (int q = 0; q < 4; q++) {
            uint32_t a2h[4], a2l[4];
            #pragma unroll
            for (int jj = 0; jj < 2; jj++) {            // n-tiles j = 2q+jj
                const int cjj = 8 * q + 4 * jj;
                const float2 bia = *(const float2*)(smem + OFF_B1 + (8 * (2 * q + jj) + cb) * 4);
                float v0 = silu(c1[cjj + 0] + bia.x);
                float v1 = silu(c1[cjj + 1] + bia.y);
                float v2 = silu(c1[cjj + 2] + bia.x);
                float v3 = silu(c1[cjj + 3] + bia.y);
                float h0 = __half2float(__float2half_rn(v0));
                float h1 = __half2float(__float2half_rn(v1));
                float h2 = __half2float(__float2half_rn(v2));
                float h3 = __half2float(__float2half_rn(v3));
                a2h[2 * jj + 0] = pack_hf2(h0, h1);
                a2h[2 * jj + 1] = pack_hf2(h2, h3);
                a2l[2 * jj + 0] = pack_hf2(v0 - h0, v1 - h1);
                a2l[2 * jj + 1] = pack_hf2(v2 - h2, v3 - h3);
            }
            #pragma unroll
            for (int jp = 0; jp < 8; jp += 2) {
                uint32_t wh0, wh1, wh2, wh3;
                ldm4(sb + OFF_W2H + jp * 8 * WPITCH2 + q * 32 + w2_off, wh0, wh1, wh2, wh3);
                mma16816(c2acc + 4 * jp,     a2h, wh0, wh1);
                mma16816(c2acc + 4 * jp,     a2l, wh0, wh1);
                mma16816(c2acc + 4 * jp + 4, a2h, wh2, wh3);
                mma16816(c2acc + 4 * jp + 4, a2l, wh2, wh3);
            }
        }

        // ---- epilogue 2: bias + silu + layer3 + quad reduce + scatter ----
        float o0a = 0.f, o1a = 0.f, o0b = 0.f, o1b = 0.f;
        #pragma unroll
        for (int j = 0; j < 8; j++) {
            const int c0 = 8 * j + cb;
            const float2 bia = *(const float2*)(smem + OFF_B2 + c0 * 4);
            const float2 w3a = *(const float2*)(smem + OFF_W3 + c0 * 8);
            const float2 w3b = *(const float2*)(smem + OFF_W3 + (c0 + 1) * 8);
            float v0 = silu(c2acc[4 * j + 0] + bia.x);
            float v1 = silu(c2acc[4 * j + 1] + bia.y);
            float v2 = silu(c2acc[4 * j + 2] + bia.x);
            float v3 = silu(c2acc[4 * j + 3] + bia.y);
            o0a = fmaf(v0, w3a.x, fmaf(v1, w3b.x, o0a));
            o1a = fmaf(v0, w3a.y, fmaf(v1, w3b.y, o1a));
            o0b = fmaf(v2, w3a.x, fmaf(v3, w3b.x, o0b));
            o1b = fmaf(v2, w3a.y, fmaf(v3, w3b.y, o1b));
        }
        #pragma unroll
        for (int m = 1; m <= 2; m <<= 1) {
            o0a += __shfl_xor_sync(0xffffffffu, o0a, m);
            o1a += __shfl_xor_sync(0xffffffffu, o1a, m);
            o0b += __shfl_xor_sync(0xffffffffu, o0b, m);
            o1b += __shfl_xor_sync(0xffffffffu, o1b, m);
        }
        if ((lane & 3) == 0) {
            const float bb0 = ((float*)(smem + OFF_B3))[0];
            const float bb1 = ((float*)(smem + OFF_B3))[1];
            const int g = lane >> 2;
            #pragma unroll
            for (int half = 0; half < 2; half++) {
                const long long item = (long long)tile * TILE + w * 16 + g + 8 * half;
                if (item < items) {
                    const int e = (int)(item >> 2);
                    const int s = (int)(item & 3);
                    int i_node;
                    if (is64) i_node = (int)((const long long*)edge)[e];
                    else      i_node = edge[e];
                    float* o = out + ((long long)i_node * S_SLOTS + s) * 2;
                    atomicAdd(o + 0, (half ? o0b : o0a) + bb0);
                    atomicAdd(o + 1, (half ? o1b : o1a) + bb1);
                }
            }
        }
        __syncthreads();   // protect X tiles before next iteration's writes
    }
}

extern "C" void kernel_launch(void* const* d_in, const int* in_sizes, int n_in,
                              void* d_out, int out_size) {
    const float* x     = (const float*)d_in[0];
    const float* theta = (const float*)d_in[1];
    const float* H     = (const float*)d_in[2];
    const int*   edge  = (const int*)d_in[3];
    const float* W1    = (const float*)d_in[4];
    const float* b1    = (const float*)d_in[5];
    const float* W2    = (const float*)d_in[6];
    const float* b2    = (const float*)d_in[7];
    const float* W3    = (const float*)d_in[8];
    const float* b3    = (const float*)d_in[9];

    const int nE = in_sizes[3] / 2;
    int nN = in_sizes[1];                  // theta has N elements
    if (nN > MAX_NODES) nN = MAX_NODES;

    const int init_n = (out_size > nN) ? out_size : nN;
    init_kernel<<<(init_n + 255) / 256, 256>>>((float*)d_out, out_size,
                                               edge, in_sizes[3], x, theta, nN);

    const long long items = (long long)nE * S_SLOTS;
    const int ntiles = (int)((items + TILE - 1) / TILE);
    int grid = 2 * 148;                    // 2 persistent CTAs per SM
    if (grid > ntiles) grid = ntiles;
    gnn_mma_kernel<<<grid, NTHREADS>>>(H, edge,
                                       W1, b1, W2, b2, W3, b3,
                                       (float*)d_out, nE, ntiles);
}

// round 13
// speedup vs baseline: 1.2837x; 1.0984x over previous
#include <cuda_runtime.h>
#include <cuda_fp16.h>
#include <cstdint>

// FrameAlignedGNNLayer3D via mma.sync (sm_100-safe HMMA path).
// R13: WARP-AUTONOMOUS tiles. R8-R12 invariant: no pipe >45%, issue ~45%,
// because per-tile __syncthreads forces all warps through feature/mma phases
// in lockstep (cross-warp X-tile dependency). Now each warp owns a private
// 32-row chunk (features by its own 32 lanes -> warp-private smem -> two
// sequential 16-row mma chunks reusing the same accumulators). Block barriers
// deleted from the loop; warps free-run and overlap MUFU/L1/tensor phases.

#define S_SLOTS 4
#define NTHREADS 256
#define NWARPS 8
#define MAX_NODES (1 << 20)

// ---- smem layout (static, ~37KB) ----
#define XPITCH 48      // 16 fp16 (32B) + 16B pad -> conflict-free ldmatrix
#define WPITCH1 48
#define WPITCH2 144    // 64 fp16 (128B) + 16B pad
#define OFF_XHI  0                              // 256 rows x 48B (warp-private 32-row regions)
#define OFF_XLO  (OFF_XHI + 256 * XPITCH)       // 12288
#define OFF_W1H  (OFF_XLO + 256 * XPITCH)       // 24576
#define OFF_W2H  (OFF_W1H + 64 * WPITCH1)       // 27648
#define OFF_B1   (OFF_W2H + 64 * WPITCH2)       // 36864
#define OFF_B2   (OFF_B1 + 256)
#define OFF_W3   (OFF_B2 + 256)                 // 64 float2 pairs
#define OFF_B3   (OFF_W3 + 512)
#define SMEM_BYTES (OFF_B3 + 16)

__device__ int g_edge_is_i64;
__device__ float4 g_node_rec[MAX_NODES];   // {x0, x1, x2, theta}

__global__ void init_kernel(float* __restrict__ out, int n,
                            const int* __restrict__ edge32, int n32,
                            const float* __restrict__ x,
                            const float* __restrict__ theta, int nN) {
    int idx = blockIdx.x * blockDim.x + threadIdx.x;
    if (idx < n) out[idx] = 0.0f;
    if (idx < nN) {
        g_node_rec[idx] = make_float4(x[3 * idx + 0], x[3 * idx + 1],
                                      x[3 * idx + 2], theta[idx]);
    }
    if (idx == 0) {
        int any_nonzero = 0;
        for (int s = 0; s < 16; s++) {
            long long pos = 1 + (long long)s * ((n32 - 2) / 16);
            pos |= 1;
            if (pos < n32) any_nonzero |= (edge32[pos] != 0);
        }
        g_edge_is_i64 = any_nonzero ? 0 : 1;
    }
}

// silu via hardware tanh: silu(v) = 0.5v * (1 + tanh(0.5v)). 1 MUFU + 2 FMA.
__device__ __forceinline__ float silu(float v) {
    float h = 0.5f * v;
    float t;
    asm("tanh.approx.f32 %0, %1;" : "=f"(t) : "f"(h));
    return fmaf(h, t, h);
}

__device__ __forceinline__ uint32_t smem_u32(const void* p) {
    uint32_t a;
    asm("{ .reg .u64 t; cvta.to.shared.u64 t, %1; cvt.u32.u64 %0, t; }" : "=r"(a) : "l"(p));
    return a;
}

__device__ __forceinline__ void ldm4(uint32_t addr, uint32_t& r0, uint32_t& r1,
                                     uint32_t& r2, uint32_t& r3) {
    asm volatile("ldmatrix.sync.aligned.m8n8.x4.shared.b16 {%0,%1,%2,%3}, [%4];"
                 : "=r"(r0), "=r"(r1), "=r"(r2), "=r"(r3) : "r"(addr));
}

__device__ __forceinline__ void mma16816(float* c, const uint32_t* a,
                                         uint32_t b0, uint32_t b1) {
    asm volatile(
        "mma.sync.aligned.m16n8k16.row.col.f32.f16.f16.f32 "
        "{%0,%1,%2,%3}, {%4,%5,%6,%7}, {%8,%9}, {%0,%1,%2,%3};"
        : "+f"(c[0]), "+f"(c[1]), "+f"(c[2]), "+f"(c[3])
        : "r"(a[0]), "r"(a[1]), "r"(a[2]), "r"(a[3]), "r"(b0), "r"(b1));
}

__device__ __forceinline__ uint32_t pack_hf2(float v0, float v1) {
    __half2 p = __floats2half2_rn(v0, v1);   // .x = v0 (low half)
    return *reinterpret_cast<uint32_t*>(&p);
}

__global__ __launch_bounds__(NTHREADS, 2)
void gnn_mma_kernel(
    const float* __restrict__ H, const int* __restrict__ edge,
    const float* __restrict__ W1, const float* __restrict__ b1,
    const float* __restrict__ W2, const float* __restrict__ b2,
    const float* __restrict__ W3, const float* __restrict__ b3,
    float* __restrict__ out, int nE, int nchunks)
{
    __shared__ __align__(16) char smem[SMEM_BYTES];
    const uint32_t sb = smem_u32(smem);

    const int t    = threadIdx.x;
    const int lane = t & 31;
    const int w    = t >> 5;           // warp id 0..7
    const int is64 = g_edge_is_i64;
    const long long items = (long long)nE * S_SLOTS;

    // ================= stage weights ONCE per block (single fp16) ============
    for (int idx = t; idx < 64 * 10; idx += NTHREADS) {
        int kk = idx / 64, n = idx % 64;
        *(__half*)(smem + OFF_W1H + n * WPITCH1 + kk * 2) = __float2half_rn(W1[kk * 64 + n]);
    }
    if (t < 64) {  // zero pad kk 10..15 of W1
        for (int kk = 10; kk < 16; kk++)
            *(__half*)(smem + OFF_W1H + t * WPITCH1 + kk * 2) = __float2half_rn(0.f);
    }
    for (int idx = t; idx < 64 * 64; idx += NTHREADS) {
        int k = idx >> 6, n = idx & 63;
        *(__half*)(smem + OFF_W2H + n * WPITCH2 + k * 2) = __float2half_rn(W2[k * 64 + n]);
    }
    if (t < 64) {
        ((float*)(smem + OFF_B1))[t] = b1[t];
        ((float*)(smem + OFF_B2))[t] = b2[t];
        ((float2*)(smem + OFF_W3))[t] = make_float2(W3[2 * t], W3[2 * t + 1]);
    }
    if (t < 2) ((float*)(smem + OFF_B3))[t] = b3[t];
    __syncthreads();   // weights visible to all warps; ONLY block barrier.

    // ================= ldmatrix address precompute =================
    const int sel = lane >> 3;
    const int r8  = lane & 7;
    // warp-private X region: rows [32w, 32w+32)
    const uint32_t a_off0 = (uint32_t)((w * 32 + r8 + (sel & 1) * 8) * XPITCH + (sel >> 1) * 16);
    const uint32_t w1_off = (uint32_t)(((sel >> 1) * 8 + r8) * WPITCH1 + (sel & 1) * 16);
    const uint32_t w2_off = (uint32_t)(((sel >> 1) * 8 + r8) * WPITCH2 + (sel & 1) * 16);
    const int cb = 2 * (lane & 3);

    const int gw = blockIdx.x * NWARPS + w;     // global warp id
    const int TW = gridDim.x * NWARPS;          // total warps

    const float bb0 = ((float*)(smem + OFF_B3))[0];
    const float bb1 = ((float*)(smem + OFF_B3))[1];

    // ================= warp-autonomous chunk loop (32 rows/chunk) ============
    for (long long chunk = gw; chunk < nchunks; chunk += TW) {

        // ---- features: every lane computes one row into warp-private smem ----
        {
            const long long item = chunk * 32 + lane;
            float f[10] = {0, 0, 0, 0, 0, 0, 0, 0, 0, 0};
            if (item < items) {
                const int e = (int)(item >> 2);
                const int s = (int)(item & 3);
                int i_node, j_node;
                if (is64) {
                    const long long* e64 = (const long long*)edge;
                    i_node = (int)e64[e]; j_node = (int)e64[(long long)nE + e];
                } else {
                    i_node = edge[e]; j_node = edge[nE + e];
                }
                const float4 ri = g_node_rec[i_node];
                const float4 rj = g_node_rec[j_node];
                const float dx0 = rj.x - ri.x;
                const float dx1 = rj.y - ri.y;
                const float dx2 = rj.z - ri.z;
                const float rxy2 = dx0 * dx0 + dx1 * dx1;
                float s2, c2; sincosf(2.0f * (rj.w - ri.w), &s2, &c2);
                float sp, cp; sincosf(atan2f(dx1, dx0) - ri.w, &sp, &cp);
                const float sgn = (dx2 > 0.0f) ? 1.0f : ((dx2 < 0.0f) ? -1.0f : 0.0f);
                const float2 hv = *(const float2*)(H + ((long long)j_node * S_SLOTS + s) * 2);
                f[0] = c2 * hv.x - s2 * hv.y;
                f[1] = s2 * hv.x + c2 * hv.y;
                f[2] = sqrtf(rxy2 + dx2 * dx2);
                f[3] = sqrtf(rxy2);
                f[4] = dx2;
                f[5] = sp;  f[6] = cp;  f[7] = s2;  f[8] = c2;  f[9] = sgn * s2;
            }
            uint32_t ph[8], pl[8];
            #pragma unroll
            for (int c = 0; c < 10; c += 2) {
                float h0 = __half2float(__float2half_rn(f[c]));
                float h1 = __half2float(__float2half_rn(f[c + 1]));
                ph[c >> 1] = pack_hf2(h0, h1);
                pl[c >> 1] = pack_hf2(f[c] - h0, f[c + 1] - h1);
            }
            ph[5] = 0u; ph[6] = 0u; ph[7] = 0u;
            pl[5] = 0u; pl[6] = 0u; pl[7] = 0u;
            const int row = w * 32 + lane;
            uint4* xh = (uint4*)(smem + OFF_XHI + row * XPITCH);
            uint4* xl = (uint4*)(smem + OFF_XLO + row * XPITCH);
            xh[0] = make_uint4(ph[0], ph[1], ph[2], ph[3]);
            xh[1] = make_uint4(ph[4], ph[5], ph[6], ph[7]);
            xl[0] = make_uint4(pl[0], pl[1], pl[2], pl[3]);
            xl[1] = make_uint4(pl[4], pl[5], pl[6], pl[7]);
        }
        __syncwarp();   // warp-private region: warp barrier suffices

        // ---- two sequential 16-row mma chunks, reusing accumulators ----
        #pragma unroll
        for (int half16 = 0; half16 < 2; half16++) {
            const uint32_t a_off = a_off0 + (uint32_t)(half16 * 16 * XPITCH);

            // layer 1: X(16x16) @ W1(16x64), 2-term fp16
            float c1[32];
            #pragma unroll
            for (int i = 0; i < 32; i++) c1[i] = 0.0f;
            {
                uint32_t a1h[4], a1l[4];
                ldm4(sb + OFF_XHI + a_off, a1h[0], a1h[1], a1h[2], a1h[3]);
                ldm4(sb + OFF_XLO + a_off, a1l[0], a1l[1], a1l[2], a1l[3]);
                #pragma unroll
                for (int jp = 0; jp < 8; jp += 2) {
                    uint32_t wh0, wh1, wh2, wh3;
                    ldm4(sb + OFF_W1H + jp * 8 * WPITCH1 + w1_off, wh0, wh1, wh2, wh3);
                    mma16816(c1 + 4 * jp,     a1h, wh0, wh1);
                    mma16816(c1 + 4 * jp,     a1l, wh0, wh1);
                    mma16816(c1 + 4 * jp + 4, a1h, wh2, wh3);
                    mma16816(c1 + 4 * jp + 4, a1l, wh2, wh3);
                }
            }

            // layer 2, fused epilogue-1, 2-term fp16
            float c2acc[32];
            #pragma unroll
            for (int i = 0; i < 32; i++) c2acc[i] = 0.0f;

            #pragma unroll
            for (int q = 0; q < 4; q++) {
                uint32_t a2h[4], a2l[4];
                #pragma unroll
                for (int jj = 0; jj < 2; jj++) {            // n-tiles j = 2q+jj
                    const int cjj = 8 * q + 4 * jj;
                    const float2 bia = *(const float2*)(smem + OFF_B1 + (8 * (2 * q + jj) + cb) * 4);
                    float v0 = silu(c1[cjj + 0] + bia.x);
                    float v1 = silu(c1[cjj + 1] + bia.y);
                    float v2 = silu(c1[cjj + 2] + bia.x);
                    float v3 = silu(c1[cjj + 3] + bia.y);
                    float h0 = __half2float(__float2half_rn(v0));
                    float h1 = __half2float(__float2half_rn(v1));
                    float h2 = __half2float(__float2half_rn(v2));
                    float h3 = __half2float(__float2half_rn(v3));
                    a2h[2 * jj + 0] = pack_hf2(h0, h1);
                    a2h[2 * jj + 1] = pack_hf2(h2, h3);
                    a2l[2 * jj + 0] = pack_hf2(v0 - h0, v1 - h1);
                    a2l[2 * jj + 1] = pack_hf2(v2 - h2, v3 - h3);
                }
                #pragma unroll
                for (int jp = 0; jp < 8; jp += 2) {
                    uint32_t wh0, wh1, wh2, wh3;
                    ldm4(sb + OFF_W2H + jp * 8 * WPITCH2 + q * 32 + w2_off, wh0, wh1, wh2, wh3);
                    mma16816(c2acc + 4 * jp,     a2h, wh0, wh1);
                    mma16816(c2acc + 4 * jp,     a2l, wh0, wh1);
                    mma16816(c2acc + 4 * jp + 4, a2h, wh2, wh3);
                    mma16816(c2acc + 4 * jp + 4, a2l, wh2, wh3);
                }
            }

            // epilogue 2: bias + silu + layer3 + quad reduce + scatter
            float o0a = 0.f, o1a = 0.f, o0b = 0.f, o1b = 0.f;
            #pragma unroll
            for (int j = 0; j < 8; j++) {
                const int c0 = 8 * j + cb;
                const float2 bia = *(const float2*)(smem + OFF_B2 + c0 * 4);
                const float2 w3a = *(const float2*)(smem + OFF_W3 + c0 * 8);
                const float2 w3b = *(const float2*)(smem + OFF_W3 + (c0 + 1) * 8);
                float v0 = silu(c2acc[4 * j + 0] + bia.x);
                float v1 = silu(c2acc[4 * j + 1] + bia.y);
                float v2 = silu(c2acc[4 * j + 2] + bia.x);
                float v3 = silu(c2acc[4 * j + 3] + bia.y);
                o0a = fmaf(v0, w3a.x, fmaf(v1, w3b.x, o0a));
                o1a = fmaf(v0, w3a.y, fmaf(v1, w3b.y, o1a));
                o0b = fmaf(v2, w3a.x, fmaf(v3, w3b.x, o0b));
                o1b = fmaf(v2, w3a.y, fmaf(v3, w3b.y, o1b));
            }
            #pragma unroll
            for (int m = 1; m <= 2; m <<= 1) {
                o0a += __shfl_xor_sync(0xffffffffu, o0a, m);
                o1a += __shfl_xor_sync(0xffffffffu, o1a, m);
                o0b += __shfl_xor_sync(0xffffffffu, o0b, m);
                o1b += __shfl_xor_sync(0xffffffffu, o1b, m);
            }
            if ((lane & 3) == 0) {
                const int g = lane >> 2;
                #pragma unroll
                for (int hh = 0; hh < 2; hh++) {
                    const long long item = chunk * 32 + half16 * 16 + g + 8 * hh;
                    if (item < items) {
                        const int e = (int)(item >> 2);
                        const int s = (int)(item & 3);
                        int i_node;
                        if (is64) i_node = (int)((const long long*)edge)[e];
                        else      i_node = edge[e];
                        float* o = out + ((long long)i_node * S_SLOTS + s) * 2;
                        atomicAdd(o + 0, (hh ? o0b : o0a) + bb0);
                        atomicAdd(o + 1, (hh ? o1b : o1a) + bb1);
                    }
                }
            }
        }
        __syncwarp();   // ldmatrix reads done before next iteration overwrites
    }
}

extern "C" void kernel_launch(void* const* d_in, const int* in_sizes, int n_in,
                              void* d_out, int out_size) {
    const float* x     = (const float*)d_in[0];
    const float* theta = (const float*)d_in[1];
    const float* H     = (const float*)d_in[2];
    const int*   edge  = (const int*)d_in[3];
    const float* W1    = (const float*)d_in[4];
    const float* b1    = (const float*)d_in[5];
    const float* W2    = (const float*)d_in[6];
    const float* b2    = (const float*)d_in[7];
    const float* W3    = (const float*)d_in[8];
    const float* b3    = (const float*)d_in[9];

    const int nE = in_sizes[3] / 2;
    int nN = in_sizes[1];                  // theta has N elements
    if (nN > MAX_NODES) nN = MAX_NODES;

    const int init_n = (out_size > nN) ? out_size : nN;
    init_kernel<<<(init_n + 255) / 256, 256>>>((float*)d_out, out_size,
                                               edge, in_sizes[3], x, theta, nN);

    const long long items = (long long)nE * S_SLOTS;
    const int nchunks = (int)((items + 31) / 32);
    int grid = 2 * 148;                    // 2 persistent CTAs per SM
    gnn_mma_kernel<<<grid, NTHREADS>>>(H, edge,
                                       W1, b1, W2, b2, W3, b3,
                                       (float*)d_out, nE, nchunks);
}

// round 14
// speedup vs baseline: 1.7595x; 1.3707x over previous
#include <cuda_runtime.h>
#include <cuda_fp16.h>
#include <cstdint>

// FrameAlignedGNNLayer3D via mma.sync (sm_100-safe HMMA path).
// R14: single-fp16 everywhere (drop the activation lo-term). R13 profile:
// issue-bound at 53%, slots split tensor 43% / fma+alu 45%. The 2-term split
// doubled mma count and paid residual-packing in the scalar pipes. fp16
// weight error already dominates (7.4e-5 measured); adding fp16 activation
// error predicts ~1-2e-4 total vs 1e-3 gate. mma/chunk 80->40, X smem and
// A-ldmatrix halve, epilogue packing halves.
// Warp-autonomous chunks (R13), persistent grid, tanh-silu retained.

#define S_SLOTS 4
#define NTHREADS 256
#define NWARPS 8
#define MAX_NODES (1 << 20)

// ---- smem layout (static, ~25KB) ----
#define XPITCH 48      // 16 fp16 (32B) + 16B pad -> conflict-free ldmatrix
#define WPITCH1 48
#define WPITCH2 144    // 64 fp16 (128B) + 16B pad
#define OFF_XHI  0                              // 256 rows x 48B (warp-private 32-row regions)
#define OFF_W1H  (OFF_XHI + 256 * XPITCH)       // 12288
#define OFF_W2H  (OFF_W1H + 64 * WPITCH1)       // 15360
#define OFF_B1   (OFF_W2H + 64 * WPITCH2)       // 24576
#define OFF_B2   (OFF_B1 + 256)
#define OFF_W3   (OFF_B2 + 256)                 // 64 float2 pairs
#define OFF_B3   (OFF_W3 + 512)
#define SMEM_BYTES (OFF_B3 + 16)

__device__ int g_edge_is_i64;
__device__ float4 g_node_rec[MAX_NODES];   // {x0, x1, x2, theta}

__global__ void init_kernel(float* __restrict__ out, int n,
                            const int* __restrict__ edge32, int n32,
                            const float* __restrict__ x,
                            const float* __restrict__ theta, int nN) {
    int idx = blockIdx.x * blockDim.x + threadIdx.x;
    if (idx < n) out[idx] = 0.0f;
    if (idx < nN) {
        g_node_rec[idx] = make_float4(x[3 * idx + 0], x[3 * idx + 1],
                                      x[3 * idx + 2], theta[idx]);
    }
    if (idx == 0) {
        int any_nonzero = 0;
        for (int s = 0; s < 16; s++) {
            long long pos = 1 + (long long)s * ((n32 - 2) / 16);
            pos |= 1;
            if (pos < n32) any_nonzero |= (edge32[pos] != 0);
        }
        g_edge_is_i64 = any_nonzero ? 0 : 1;
    }
}

// silu via hardware tanh: silu(v) = 0.5v * (1 + tanh(0.5v)). 1 MUFU + 2 FMA.
__device__ __forceinline__ float silu(float v) {
    float h = 0.5f * v;
    float t;
    asm("tanh.approx.f32 %0, %1;" : "=f"(t) : "f"(h));
    return fmaf(h, t, h);
}

__device__ __forceinline__ uint32_t smem_u32(const void* p) {
    uint32_t a;
    asm("{ .reg .u64 t; cvta.to.shared.u64 t, %1; cvt.u32.u64 %0, t; }" : "=r"(a) : "l"(p));
    return a;
}

__device__ __forceinline__ void ldm4(uint32_t addr, uint32_t& r0, uint32_t& r1,
                                     uint32_t& r2, uint32_t& r3) {
    asm volatile("ldmatrix.sync.aligned.m8n8.x4.shared.b16 {%0,%1,%2,%3}, [%4];"
                 : "=r"(r0), "=r"(r1), "=r"(r2), "=r"(r3) : "r"(addr));
}

__device__ __forceinline__ void mma16816(float* c, const uint32_t* a,
                                         uint32_t b0, uint32_t b1) {
    asm volatile(
        "mma.sync.aligned.m16n8k16.row.col.f32.f16.f16.f32 "
        "{%0,%1,%2,%3}, {%4,%5,%6,%7}, {%8,%9}, {%0,%1,%2,%3};"
        : "+f"(c[0]), "+f"(c[1]), "+f"(c[2]), "+f"(c[3])
        : "r"(a[0]), "r"(a[1]), "r"(a[2]), "r"(a[3]), "r"(b0), "r"(b1));
}

__device__ __forceinline__ uint32_t pack_hf2(float v0, float v1) {
    __half2 p = __floats2half2_rn(v0, v1);   // .x = v0 (low half)
    return *reinterpret_cast<uint32_t*>(&p);
}

__global__ __launch_bounds__(NTHREADS, 2)
void gnn_mma_kernel(
    const float* __restrict__ H, const int* __restrict__ edge,
    const float* __restrict__ W1, const float* __restrict__ b1,
    const float* __restrict__ W2, const float* __restrict__ b2,
    const float* __restrict__ W3, const float* __restrict__ b3,
    float* __restrict__ out, int nE, int nchunks)
{
    __shared__ __align__(16) char smem[SMEM_BYTES];
    const uint32_t sb = smem_u32(smem);

    const int t    = threadIdx.x;
    const int lane = t & 31;
    const int w    = t >> 5;           // warp id 0..7
    const int is64 = g_edge_is_i64;
    const long long items = (long long)nE * S_SLOTS;

    // ================= stage weights ONCE per block (single fp16) ============
    for (int idx = t; idx < 64 * 10; idx += NTHREADS) {
        int kk = idx / 64, n = idx % 64;
        *(__half*)(smem + OFF_W1H + n * WPITCH1 + kk * 2) = __float2half_rn(W1[kk * 64 + n]);
    }
    if (t < 64) {  // zero pad kk 10..15 of W1
        for (int kk = 10; kk < 16; kk++)
            *(__half*)(smem + OFF_W1H + t * WPITCH1 + kk * 2) = __float2half_rn(0.f);
    }
    for (int idx = t; idx < 64 * 64; idx += NTHREADS) {
        int k = idx >> 6, n = idx & 63;
        *(__half*)(smem + OFF_W2H + n * WPITCH2 + k * 2) = __float2half_rn(W2[k * 64 + n]);
    }
    if (t < 64) {
        ((float*)(smem + OFF_B1))[t] = b1[t];
        ((float*)(smem + OFF_B2))[t] = b2[t];
        ((float2*)(smem + OFF_W3))[t] = make_float2(W3[2 * t], W3[2 * t + 1]);
    }
    if (t < 2) ((float*)(smem + OFF_B3))[t] = b3[t];
    __syncthreads();   // weights visible to all warps; ONLY block barrier.

    // ================= ldmatrix address precompute =================
    const int sel = lane >> 3;
    const int r8  = lane & 7;
    // warp-private X region: rows [32w, 32w+32)
    const uint32_t a_off0 = (uint32_t)((w * 32 + r8 + (sel & 1) * 8) * XPITCH + (sel >> 1) * 16);
    const uint32_t w1_off = (uint32_t)(((sel >> 1) * 8 + r8) * WPITCH1 + (sel & 1) * 16);
    const uint32_t w2_off = (uint32_t)(((sel >> 1) * 8 + r8) * WPITCH2 + (sel & 1) * 16);
    const int cb = 2 * (lane & 3);

    const int gw = blockIdx.x * NWARPS + w;     // global warp id
    const int TW = gridDim.x * NWARPS;          // total warps

    const float bb0 = ((float*)(smem + OFF_B3))[0];
    const float bb1 = ((float*)(smem + OFF_B3))[1];

    // ================= warp-autonomous chunk loop (32 rows/chunk) ============
    for (long long chunk = gw; chunk < nchunks; chunk += TW) {

        // ---- features: every lane computes one row into warp-private smem ----
        {
            const long long item = chunk * 32 + lane;
            float f[10] = {0, 0, 0, 0, 0, 0, 0, 0, 0, 0};
            if (item < items) {
                const int e = (int)(item >> 2);
                const int s = (int)(item & 3);
                int i_node, j_node;
                if (is64) {
                    const long long* e64 = (const long long*)edge;
                    i_node = (int)e64[e]; j_node = (int)e64[(long long)nE + e];
                } else {
                    i_node = edge[e]; j_node = edge[nE + e];
                }
                const float4 ri = g_node_rec[i_node];
                const float4 rj = g_node_rec[j_node];
                const float dx0 = rj.x - ri.x;
                const float dx1 = rj.y - ri.y;
                const float dx2 = rj.z - ri.z;
                const float rxy2 = dx0 * dx0 + dx1 * dx1;
                float s2, c2; sincosf(2.0f * (rj.w - ri.w), &s2, &c2);
                float sp, cp; sincosf(atan2f(dx1, dx0) - ri.w, &sp, &cp);
                const float sgn = (dx2 > 0.0f) ? 1.0f : ((dx2 < 0.0f) ? -1.0f : 0.0f);
                const float2 hv = *(const float2*)(H + ((long long)j_node * S_SLOTS + s) * 2);
                f[0] = c2 * hv.x - s2 * hv.y;
                f[1] = s2 * hv.x + c2 * hv.y;
                f[2] = sqrtf(rxy2 + dx2 * dx2);
                f[3] = sqrtf(rxy2);
                f[4] = dx2;
                f[5] = sp;  f[6] = cp;  f[7] = s2;  f[8] = c2;  f[9] = sgn * s2;
            }
            uint32_t ph[8];
            #pragma unroll
            for (int c = 0; c < 10; c += 2)
                ph[c >> 1] = pack_hf2(f[c], f[c + 1]);
            ph[5] = 0u; ph[6] = 0u; ph[7] = 0u;
            const int row = w * 32 + lane;
            uint4* xh = (uint4*)(smem + OFF_XHI + row * XPITCH);
            xh[0] = make_uint4(ph[0], ph[1], ph[2], ph[3]);
            xh[1] = make_uint4(ph[4], ph[5], ph[6], ph[7]);
        }
        __syncwarp();   // warp-private region: warp barrier suffices

        // ---- two sequential 16-row mma chunks, reusing accumulators ----
        #pragma unroll
        for (int half16 = 0; half16 < 2; half16++) {
            const uint32_t a_off = a_off0 + (uint32_t)(half16 * 16 * XPITCH);

            // layer 1: X(16x16) @ W1(16x64), single fp16
            float c1[32];
            #pragma unroll
            for (int i = 0; i < 32; i++) c1[i] = 0.0f;
            {
                uint32_t a1h[4];
                ldm4(sb + OFF_XHI + a_off, a1h[0], a1h[1], a1h[2], a1h[3]);
                #pragma unroll
                for (int jp = 0; jp < 8; jp += 2) {
                    uint32_t wh0, wh1, wh2, wh3;
                    ldm4(sb + OFF_W1H + jp * 8 * WPITCH1 + w1_off, wh0, wh1, wh2, wh3);
                    mma16816(c1 + 4 * jp,     a1h, wh0, wh1);
                    mma16816(c1 + 4 * jp + 4, a1h, wh2, wh3);
                }
            }

            // layer 2, fused epilogue-1, single fp16
            float c2acc[32];
            #pragma unroll
            for (int i = 0; i < 32; i++) c2acc[i] = 0.0f;

            #pragma unroll
            for (int q = 0; q < 4; q++) {
                uint32_t a2h[4];
                #pragma unroll
                for (int jj = 0; jj < 2; jj++) {            // n-tiles j = 2q+jj
                    const int cjj = 8 * q + 4 * jj;
                    const float2 bia = *(const float2*)(smem + OFF_B1 + (8 * (2 * q + jj) + cb) * 4);
                    float v0 = silu(c1[cjj + 0] + bia.x);
                    float v1 = silu(c1[cjj + 1] + bia.y);
                    float v2 = silu(c1[cjj + 2] + bia.x);
                    float v3 = silu(c1[cjj + 3] + bia.y);
                    a2h[2 * jj + 0] = pack_hf2(v0, v1);
                    a2h[2 * jj + 1] = pack_hf2(v2, v3);
                }
                #pragma unroll
                for (int jp = 0; jp < 8; jp += 2) {
                    uint32_t wh0, wh1, wh2, wh3;
                    ldm4(sb + OFF_W2H + jp * 8 * WPITCH2 + q * 32 + w2_off, wh0, wh1, wh2, wh3);
                    mma16816(c2acc + 4 * jp,     a2h, wh0, wh1);
                    mma16816(c2acc + 4 * jp + 4, a2h, wh2, wh3);
                }
            }

            // epilogue 2: bias + silu + layer3 + quad reduce + scatter
            float o0a = 0.f, o1a = 0.f, o0b = 0.f, o1b = 0.f;
            #pragma unroll
            for (int j = 0; j < 8; j++) {
                const int c0 = 8 * j + cb;
                const float2 bia = *(const float2*)(smem + OFF_B2 + c0 * 4);
                const float2 w3a = *(const float2*)(smem + OFF_W3 + c0 * 8);
                const float2 w3b = *(const float2*)(smem + OFF_W3 + (c0 + 1) * 8);
                float v0 = silu(c2acc[4 * j + 0] + bia.x);
                float v1 = silu(c2acc[4 * j + 1] + bia.y);
                float v2 = silu(c2acc[4 * j + 2] + bia.x);
                float v3 = silu(c2acc[4 * j + 3] + bia.y);
                o0a = fmaf(v0, w3a.x, fmaf(v1, w3b.x, o0a));
                o1a = fmaf(v0, w3a.y, fmaf(v1, w3b.y, o1a));
                o0b = fmaf(v2, w3a.x, fmaf(v3, w3b.x, o0b));
                o1b = fmaf(v2, w3a.y, fmaf(v3, w3b.y, o1b));
            }
            #pragma unroll
            for (int m = 1; m <= 2; m <<= 1) {
                o0a += __shfl_xor_sync(0xffffffffu, o0a, m);
                o1a += __shfl_xor_sync(0xffffffffu, o1a, m);
                o0b += __shfl_xor_sync(0xffffffffu, o0b, m);
                o1b += __shfl_xor_sync(0xffffffffu, o1b, m);
            }
            if ((lane & 3) == 0) {
                const int g = lane >> 2;
                #pragma unroll
                for (int hh = 0; hh < 2; hh++) {
                    const long long item = chunk * 32 + half16 * 16 + g + 8 * hh;
                    if (item < items) {
                        const int e = (int)(item >> 2);
                        const int s = (int)(item & 3);
                        int i_node;
                        if (is64) i_node = (int)((const long long*)edge)[e];
                        else      i_node = edge[e];
                        float* o = out + ((long long)i_node * S_SLOTS + s) * 2;
                        atomicAdd(o + 0, (hh ? o0b : o0a) + bb0);
                        atomicAdd(o + 1, (hh ? o1b : o1a) + bb1);
                    }
                }
            }
        }
        __syncwarp();   // ldmatrix reads done before next iteration overwrites
    }
}

extern "C" void kernel_launch(void* const* d_in, const int* in_sizes, int n_in,
                              void* d_out, int out_size) {
    const float* x     = (const float*)d_in[0];
    const float* theta = (const float*)d_in[1];
    const float* H     = (const float*)d_in[2];
    const int*   edge  = (const int*)d_in[3];
    const float* W1    = (const float*)d_in[4];
    const float* b1    = (const float*)d_in[5];
    const float* W2    = (const float*)d_in[6];
    const float* b2    = (const float*)d_in[7];
    const float* W3    = (const float*)d_in[8];
    const float* b3    = (const float*)d_in[9];

    const int nE = in_sizes[3] / 2;
    int nN = in_sizes[1];                  // theta has N elements
    if (nN > MAX_NODES) nN = MAX_NODES;

    const int init_n = (out_size > nN) ? out_size : nN;
    init_kernel<<<(init_n + 255) / 256, 256>>>((float*)d_out, out_size,
                                               edge, in_sizes[3], x, theta, nN);

    const long long items = (long long)nE * S_SLOTS;
    const int nchunks = (int)((items + 31) / 32);
    int grid = 2 * 148;                    // 2 persistent CTAs per SM
    gnn_mma_kernel<<<grid, NTHREADS>>>(H, edge,
                                       W1, b1, W2, b2, W3, b3,
                                       (float*)d_out, nE, nchunks);
}